// round 14
// baseline (speedup 1.0000x reference)
#include <cuda_runtime.h>
#include <cuda_bf16.h>
#include <cuda_fp8.h>
#include <cstdint>

// ---------------------------------------------------------------------------
// Problem constants
// ---------------------------------------------------------------------------
#define B_ROWS 4096
#define NTOT   8192          // 2B
#define D      512
#define NT     64            // NTOT / 128 tiles per dim
#define NPAIRS (NT * (NT + 1) / 2)    // 2080 upper-tri tiles
#define NCTA   296                    // 2 CTAs x 148 SMs (persistent)
#define TEMP_INV 2.0f
#define LOG2E_2  2.8853900817779268f  // 2/ln2 : exp(2x)=2^(x*2/ln2)
#define LN2      0.6931471805599453f
#define Z_SCALE  16.0f                // fp8 pre-scale (avoid subnormals)
// accumulated sim is scaled by Z_SCALE^2=256; fold into exp2 multiplier
#define EPI_MUL  (LOG2E_2 / 256.0f)

// ---------------------------------------------------------------------------
// Scratch (__device__ globals; no allocation allowed)
// ---------------------------------------------------------------------------
__device__ __nv_bfloat16 g_zb[(size_t)NTOT * D];   // 8 MB normalized bf16 (pos dot)
__device__ uint8_t       g_z8[(size_t)NTOT * D];   // 4 MB normalized e4m3*16
__device__ float g_partial[(size_t)NT * NTOT];     // 2 MB partial row sums
__device__ float g_rowloss[NTOT];
__device__ int   g_ctr;                            // last-block counter (resets)

// ---------------------------------------------------------------------------
// Helpers
// ---------------------------------------------------------------------------
__device__ __forceinline__ float fast_exp2(float x) {
    float r; asm("ex2.approx.ftz.f32 %0, %1;" : "=f"(r) : "f"(x)); return r;
}
__device__ __forceinline__ float fast_log(float x) {
    float r; asm("lg2.approx.f32 %0, %1;" : "=f"(r) : "f"(x)); return r * LN2;
}

#define CP_ASYNC16(dst32, srcp)                                              \
    asm volatile("cp.async.cg.shared.global [%0], [%1], 16;\n" ::            \
                     "r"(dst32), "l"(srcp))
#define CP_COMMIT  asm volatile("cp.async.commit_group;\n" ::)
#define CP_WAIT(n) asm volatile("cp.async.wait_group %0;\n" :: "n"(n))

// ---------------------------------------------------------------------------
// K1: row-normalize (eps clamp), emit bf16 (pos-dot) and e4m3*16 (GEMM).
// 128 threads / block, 1 row per block.
// ---------------------------------------------------------------------------
__global__ void normalize_kernel(const float* __restrict__ h1,
                                 const float* __restrict__ h2) {
    int row = blockIdx.x;
    const float* src = (row < B_ROWS) ? (h1 + (size_t)row * D)
                                      : (h2 + (size_t)(row - B_ROWS) * D);
    int t = threadIdx.x;  // 0..127
    float4 v = reinterpret_cast<const float4*>(src)[t];
    float s = v.x * v.x + v.y * v.y + v.z * v.z + v.w * v.w;
    #pragma unroll
    for (int o = 16; o > 0; o >>= 1) s += __shfl_xor_sync(0xffffffff, s, o);
    __shared__ float ws[4];
    if ((t & 31) == 0) ws[t >> 5] = s;
    __syncthreads();
    float tot = ws[0] + ws[1] + ws[2] + ws[3];
    float scale = 1.0f / fmaxf(sqrtf(tot), 1e-8f);

    __nv_bfloat162* dst =
        reinterpret_cast<__nv_bfloat162*>(g_zb + (size_t)row * D);
    dst[2 * t]     = __floats2bfloat162_rn(v.x * scale, v.y * scale);
    dst[2 * t + 1] = __floats2bfloat162_rn(v.z * scale, v.w * scale);

    float s8 = scale * Z_SCALE;
    float2 p0 = make_float2(v.x * s8, v.y * s8);
    float2 p1 = make_float2(v.z * s8, v.w * s8);
    uint32_t lo = __nv_cvt_float2_to_fp8x2(p0, __NV_SATFINITE, __NV_E4M3);
    uint32_t hi = __nv_cvt_float2_to_fp8x2(p1, __NV_SATFINITE, __NV_E4M3);
    reinterpret_cast<uint32_t*>(g_z8)[(size_t)row * (D / 4) + t] =
        (lo & 0xffffu) | (hi << 16);
}

// ---------------------------------------------------------------------------
// K2: persistent fused FP8 GEMM + exp + row/col partial sums.
// 296 CTAs loop over 2080 upper-tri tiles. The cp.async load iterator runs
// 3 stages ahead of compute CONTINUOUSLY across tile boundaries: pipeline
// fills once per CTA, epilogues overlap with next-tile loads.
// 4-slot ring, BK=64B (8 K-steps/tile). 8 warps (4M x 2N), warp tile 32x64,
// mma.sync.m16n8k32 e4m3 f32acc. 80B row pitch -> conflict-free ldmatrix.
// ---------------------------------------------------------------------------
#define BKB 64               // K bytes per stage
#define NKSTEP (D / BKB)     // 8
#define RPITCH 80            // padded row pitch (bytes)
#define A_BYTES (128 * RPITCH)       // 10240
#define STAGE_BYTES (2 * A_BYTES)    // 20480 (A then B)
#define DYN_SMEM (4 * STAGE_BYTES)   // 81920

__device__ __forceinline__ uint32_t smem_u32(const void* p) {
    uint32_t a;
    asm("{ .reg .u64 t; cvta.to.shared.u64 t, %1; cvt.u32.u64 %0, t; }"
        : "=r"(a) : "l"(p));
    return a;
}

__device__ __forceinline__ void decode_tile(int b, int& ti, int& tj) {
    int x = (int)((129.0f - sqrtf(16641.0f - 8.0f * (float)b)) * 0.5f);
    while ((x + 1) * (129 - (x + 1)) / 2 <= b) ++x;
    while (x * (129 - x) / 2 > b) --x;
    ti = x;
    tj = x + (b - x * (129 - x) / 2);
}

__device__ __forceinline__ void load_stage(uint32_t sbase,
                                           const uint8_t* gA,
                                           const uint8_t* gB,
                                           int kt, int t) {
    const int koff = kt * BKB;
    #pragma unroll
    for (int p = 0; p < 2; ++p) {
        int idx = t + p * 256;          // 0..511
        int row = idx >> 2;             // 0..127
        int cc = idx & 3;               // 16B chunk within 64B
        uint32_t so = (uint32_t)(row * RPITCH + cc * 16);
        const size_t go = (size_t)row * D + koff + cc * 16;
        CP_ASYNC16(sbase + so, gA + go);
        CP_ASYNC16(sbase + A_BYTES + so, gB + go);
    }
}

__global__ __launch_bounds__(256, 2) void gemm_exp_kernel() {
    extern __shared__ uint8_t smem[];
    __shared__ float rowsum[2][128];
    __shared__ float colsum_s[4][128];

    const int t = threadIdx.x;
    const int lane = t & 31;
    const int wid = t >> 5;
    const int wm = wid & 3;              // warp row 0..3
    const int wn = wid >> 2;             // warp col 0..1
    const uint32_t sb = smem_u32(smem);

    // total compute steps for this CTA
    const int ntiles = (NPAIRS - blockIdx.x + gridDim.x - 1) / gridDim.x;
    const int total = ntiles * NKSTEP;

    // ---- load iterator state (3 stages ahead, continuous across tiles) ----
    int lb = blockIdx.x;                 // load tile linear index
    int lti, ltj;
    decode_tile(lb, lti, ltj);
    const uint8_t* lA = g_z8 + (size_t)lti * 128 * D;
    const uint8_t* lB = g_z8 + (size_t)ltj * 128 * D;
    int lkt = 0;
    int issued = 0;

    #define ISSUE_ONE()                                                      \
        do {                                                                 \
            load_stage(sb + (uint32_t)(issued & 3) * STAGE_BYTES,            \
                       lA, lB, lkt, t);                                      \
            CP_COMMIT;                                                       \
            ++issued;                                                        \
            if (++lkt == NKSTEP) {                                           \
                lkt = 0;                                                     \
                lb += gridDim.x;                                             \
                if (lb < NPAIRS) {                                           \
                    decode_tile(lb, lti, ltj);                               \
                    lA = g_z8 + (size_t)lti * 128 * D;                       \
                    lB = g_z8 + (size_t)ltj * 128 * D;                       \
                }                                                            \
            }                                                                \
        } while (0)

    // prologue: fill 3 stages
    if (issued < total) ISSUE_ONE();
    if (issued < total) ISSUE_ONE();
    if (issued < total) ISSUE_ONE();

    int s = 0;   // global compute step
    for (int cb = blockIdx.x; cb < NPAIRS; cb += gridDim.x) {
        int ti, tj;
        decode_tile(cb, ti, tj);
        const bool diag = (ti == tj);

        float c[2][8][4];
        #pragma unroll
        for (int mi = 0; mi < 2; ++mi)
            #pragma unroll
            for (int ni = 0; ni < 8; ++ni)
                #pragma unroll
                for (int q = 0; q < 4; ++q) c[mi][ni][q] = 0.0f;

        for (int kt = 0; kt < NKSTEP; ++kt, ++s) {
            const int ahead = issued - s;   // groups in flight incl. step s
            if (ahead >= 3)      CP_WAIT(2);
            else if (ahead == 2) CP_WAIT(1);
            else                 CP_WAIT(0);
            __syncthreads();
            // issue next stage into slot (s-1)&3 — all warps finished
            // reading it at step s-1 (barrier above enforces)
            if (issued < total) ISSUE_ONE();

            const uint32_t aBase = sb + (uint32_t)(s & 3) * STAGE_BYTES;
            const uint32_t bBase = aBase + A_BYTES;

            #pragma unroll
            for (int ks = 0; ks < 2; ++ks) {
                const int kb = ks * 32;      // byte offset of k32 block
                uint32_t af[2][4];
                #pragma unroll
                for (int mi = 0; mi < 2; ++mi) {
                    int r = wm * 32 + mi * 16 + (lane & 15);
                    int colb = kb + (lane >> 4) * 16;
                    uint32_t addr = aBase + r * RPITCH + colb;
                    asm volatile(
                        "ldmatrix.sync.aligned.m8n8.x4.shared.b16 "
                        "{%0,%1,%2,%3}, [%4];"
                        : "=r"(af[mi][0]), "=r"(af[mi][1]),
                          "=r"(af[mi][2]), "=r"(af[mi][3])
                        : "r"(addr));
                }
                uint32_t bfr[8][2];
                #pragma unroll
                for (int nb = 0; nb < 4; ++nb) {
                    int nr = wn * 64 + nb * 16 + ((lane >> 4) & 1) * 8 +
                             (lane & 7);
                    int colb = kb + ((lane >> 3) & 1) * 16;
                    uint32_t addr = bBase + nr * RPITCH + colb;
                    asm volatile(
                        "ldmatrix.sync.aligned.m8n8.x4.shared.b16 "
                        "{%0,%1,%2,%3}, [%4];"
                        : "=r"(bfr[2 * nb][0]), "=r"(bfr[2 * nb][1]),
                          "=r"(bfr[2 * nb + 1][0]), "=r"(bfr[2 * nb + 1][1])
                        : "r"(addr));
                }
                #pragma unroll
                for (int mi = 0; mi < 2; ++mi)
                    #pragma unroll
                    for (int ni = 0; ni < 8; ++ni) {
                        asm volatile(
                            "mma.sync.aligned.m16n8k32.row.col"
                            ".f32.e4m3.e4m3.f32 "
                            "{%0,%1,%2,%3}, {%4,%5,%6,%7}, {%8,%9}, "
                            "{%0,%1,%2,%3};"
                            : "+f"(c[mi][ni][0]), "+f"(c[mi][ni][1]),
                              "+f"(c[mi][ni][2]), "+f"(c[mi][ni][3])
                            : "r"(af[mi][0]), "r"(af[mi][1]),
                              "r"(af[mi][2]), "r"(af[mi][3]),
                              "r"(bfr[ni][0]), "r"(bfr[ni][1]));
                    }
            }
        }

        // --- Epilogue (overlaps with next tile's cp.async loads) ---
        // c := exp(2*sim), diag masked. acc = 256*sim.
        #pragma unroll
        for (int mi = 0; mi < 2; ++mi)
            #pragma unroll
            for (int rr = 0; rr < 2; ++rr) {
                int grow = ti * 128 + wm * 32 + mi * 16 + rr * 8 + (lane >> 2);
                #pragma unroll
                for (int ni = 0; ni < 8; ++ni)
                    #pragma unroll
                    for (int q = 0; q < 2; ++q) {
                        int gcol = tj * 128 + wn * 64 + ni * 8 +
                                   2 * (lane & 3) + q;
                        float v = c[mi][ni][rr * 2 + q];
                        c[mi][ni][rr * 2 + q] =
                            (grow == gcol) ? 0.0f : fast_exp2(v * EPI_MUL);
                    }
            }

        // Row sums (rows of block ti)
        #pragma unroll
        for (int mi = 0; mi < 2; ++mi)
            #pragma unroll
            for (int rr = 0; rr < 2; ++rr) {
                int lrow = wm * 32 + mi * 16 + rr * 8 + (lane >> 2);
                float sv = 0.0f;
                #pragma unroll
                for (int ni = 0; ni < 8; ++ni)
                    #pragma unroll
                    for (int q = 0; q < 2; ++q) sv += c[mi][ni][rr * 2 + q];
                sv += __shfl_xor_sync(0xffffffff, sv, 1);
                sv += __shfl_xor_sync(0xffffffff, sv, 2);
                if ((lane & 3) == 0) rowsum[wn][lrow] = sv;
            }

        // Column sums (rows of block tj) — only off-diagonal tiles
        if (!diag) {
            #pragma unroll
            for (int ni = 0; ni < 8; ++ni)
                #pragma unroll
                for (int q = 0; q < 2; ++q) {
                    float sv = c[0][ni][q] + c[0][ni][2 + q] +
                               c[1][ni][q] + c[1][ni][2 + q];
                    sv += __shfl_xor_sync(0xffffffff, sv, 4);
                    sv += __shfl_xor_sync(0xffffffff, sv, 8);
                    sv += __shfl_xor_sync(0xffffffff, sv, 16);
                    if ((lane >> 2) == 0) {
                        int lcol = wn * 64 + ni * 8 + 2 * (lane & 3) + q;
                        colsum_s[wm][lcol] = sv;
                    }
                }
        }
        __syncthreads();

        if (t < 128) {
            g_partial[(size_t)tj * NTOT + (size_t)ti * 128 + t] =
                rowsum[0][t] + rowsum[1][t];
            if (!diag)
                g_partial[(size_t)ti * NTOT + (size_t)tj * 128 + t] =
                    colsum_s[0][t] + colsum_s[1][t] +
                    colsum_s[2][t] + colsum_s[3][t];
        }
        __syncthreads();   // protect rowsum/colsum before next tile's writes
    }
    #undef ISSUE_ONE
}

// ---------------------------------------------------------------------------
// K3: per-row loss + fused deterministic finalize (round-8 proven shape).
// One warp per row; 1024 blocks x 256 threads.
// ---------------------------------------------------------------------------
__device__ __forceinline__ float bf2dot(uint32_t a, uint32_t b) {
    float2 fa = __bfloat1622float2(*reinterpret_cast<__nv_bfloat162*>(&a));
    float2 fb = __bfloat1622float2(*reinterpret_cast<__nv_bfloat162*>(&b));
    return fa.x * fb.x + fa.y * fb.y;
}

__global__ void rowloss_kernel(float* __restrict__ out) {
    int wid = threadIdx.x >> 5;
    int lane = threadIdx.x & 31;
    int row = blockIdx.x * 8 + wid;

    float s = g_partial[(size_t)lane * NTOT + row] +
              g_partial[(size_t)(lane + 32) * NTOT + row];

    int prow = (row < B_ROWS) ? row + B_ROWS : row - B_ROWS;
    const uint4* a = reinterpret_cast<const uint4*>(g_zb + (size_t)row * D);
    const uint4* bp = reinterpret_cast<const uint4*>(g_zb + (size_t)prow * D);
    float dot = 0.0f;
    #pragma unroll
    for (int p = 0; p < 2; ++p) {
        uint4 av = a[lane * 2 + p];
        uint4 bv = bp[lane * 2 + p];
        dot += bf2dot(av.x, bv.x) + bf2dot(av.y, bv.y) +
               bf2dot(av.z, bv.z) + bf2dot(av.w, bv.w);
    }
    #pragma unroll
    for (int o = 16; o > 0; o >>= 1) {
        s   += __shfl_xor_sync(0xffffffff, s, o);
        dot += __shfl_xor_sync(0xffffffff, dot, o);
    }
    if (lane == 0) g_rowloss[row] = fast_log(s) - TEMP_INV * dot;

    // last-block finalize (deterministic fixed-order sum; no FP atomics)
    __shared__ int is_last;
    __shared__ float sm[256];
    __threadfence();
    __syncthreads();
    if (threadIdx.x == 0)
        is_last = (atomicAdd(&g_ctr, 1) == (int)gridDim.x - 1);
    __syncthreads();
    if (is_last) {
        __threadfence();
        float acc = 0.0f;
        for (int i = threadIdx.x; i < NTOT; i += 256) acc += g_rowloss[i];
        sm[threadIdx.x] = acc;
        __syncthreads();
        #pragma unroll
        for (int st = 128; st > 0; st >>= 1) {
            if (threadIdx.x < st) sm[threadIdx.x] += sm[threadIdx.x + st];
            __syncthreads();
        }
        if (threadIdx.x == 0) {
            g_ctr = 0;   // reset for next graph replay
            out[0] = sm[0] * (1.0f / NTOT);
        }
    }
}

// ---------------------------------------------------------------------------
extern "C" void kernel_launch(void* const* d_in, const int* in_sizes, int n_in,
                              void* d_out, int out_size) {
    const float* h1 = (const float*)d_in[0];
    const float* h2 = (const float*)d_in[1];
    float* out = (float*)d_out;

    static bool attr_set = false;
    if (!attr_set) {
        cudaFuncSetAttribute(gemm_exp_kernel,
                             cudaFuncAttributeMaxDynamicSharedMemorySize,
                             DYN_SMEM);
        attr_set = true;
    }

    normalize_kernel<<<NTOT, 128>>>(h1, h2);
    gemm_exp_kernel<<<NCTA, 256, DYN_SMEM>>>();
    rowloss_kernel<<<NTOT / 8, 256>>>(out);
}

// round 16
// speedup vs baseline: 1.1626x; 1.1626x over previous
#include <cuda_runtime.h>
#include <cuda_bf16.h>
#include <cuda_fp8.h>
#include <cstdint>

// ---------------------------------------------------------------------------
// Problem constants
// ---------------------------------------------------------------------------
#define B_ROWS 4096
#define NTOT   8192          // 2B
#define D      512
#define NT     64            // NTOT / 128 tiles per dim
#define TEMP_INV 2.0f
#define LOG2E_2  2.8853900817779268f  // 2/ln2 : exp(2x)=2^(x*2/ln2)
#define LN2      0.6931471805599453f
#define Z_SCALE  16.0f                // fp8 pre-scale (avoid subnormals)
// accumulated sim is scaled by Z_SCALE^2=256; fold into exp2 multiplier
#define EPI_MUL  (LOG2E_2 / 256.0f)
#define POS_MUL  (TEMP_INV / 256.0f)  // pos term: 2*sim = acc * 2/256

// ---------------------------------------------------------------------------
// Scratch (__device__ globals; no allocation allowed)
// ---------------------------------------------------------------------------
__device__ uint8_t g_z8[(size_t)NTOT * D];         // 4 MB normalized e4m3*16
__device__ float g_partial[(size_t)NT * NTOT];     // 2 MB partial row sums
__device__ float g_pos[B_ROWS];                    // 2*sim(i, i+B), harvested
__device__ float g_rowloss[NTOT];
__device__ int   g_ctr;                            // last-block counter (resets)

// ---------------------------------------------------------------------------
// Helpers
// ---------------------------------------------------------------------------
__device__ __forceinline__ float fast_exp2(float x) {
    float r; asm("ex2.approx.ftz.f32 %0, %1;" : "=f"(r) : "f"(x)); return r;
}
__device__ __forceinline__ float fast_log(float x) {
    float r; asm("lg2.approx.f32 %0, %1;" : "=f"(r) : "f"(x)); return r * LN2;
}

#define CP_ASYNC16(dst32, srcp)                                              \
    asm volatile("cp.async.cg.shared.global [%0], [%1], 16;\n" ::            \
                     "r"(dst32), "l"(srcp))
#define CP_COMMIT  asm volatile("cp.async.commit_group;\n" ::)
#define CP_WAIT(n) asm volatile("cp.async.wait_group %0;\n" :: "n"(n))

// ---------------------------------------------------------------------------
// K1: row-normalize (eps clamp), emit e4m3*16 only (no bf16 copy needed —
// the positive-pair dot is harvested from the GEMM itself).
// 128 threads / block, 1 row per block.
// ---------------------------------------------------------------------------
__global__ void normalize_kernel(const float* __restrict__ h1,
                                 const float* __restrict__ h2) {
    int row = blockIdx.x;
    const float* src = (row < B_ROWS) ? (h1 + (size_t)row * D)
                                      : (h2 + (size_t)(row - B_ROWS) * D);
    int t = threadIdx.x;  // 0..127
    float4 v = reinterpret_cast<const float4*>(src)[t];
    float s = v.x * v.x + v.y * v.y + v.z * v.z + v.w * v.w;
    #pragma unroll
    for (int o = 16; o > 0; o >>= 1) s += __shfl_xor_sync(0xffffffff, s, o);
    __shared__ float ws[4];
    if ((t & 31) == 0) ws[t >> 5] = s;
    __syncthreads();
    float tot = ws[0] + ws[1] + ws[2] + ws[3];
    float scale = 1.0f / fmaxf(sqrtf(tot), 1e-8f);

    float s8 = scale * Z_SCALE;
    float2 p0 = make_float2(v.x * s8, v.y * s8);
    float2 p1 = make_float2(v.z * s8, v.w * s8);
    uint32_t lo = __nv_cvt_float2_to_fp8x2(p0, __NV_SATFINITE, __NV_E4M3);
    uint32_t hi = __nv_cvt_float2_to_fp8x2(p1, __NV_SATFINITE, __NV_E4M3);
    reinterpret_cast<uint32_t*>(g_z8)[(size_t)row * (D / 4) + t] =
        (lo & 0xffffu) | (hi << 16);
}

// ---------------------------------------------------------------------------
// K2: fused FP8 GEMM tile + exp + row/col partial sums (round-8 proven
// shape: 64x64 grid, early-exit lower triangle). 4-stage cp.async ring,
// BK=64B (8 K-steps). 8 warps (4M x 2N), warp tile 32x64,
// mma.sync.m16n8k32 e4m3 f32acc. 80B row pitch -> conflict-free ldmatrix.
// Tiles with tj == ti+32 also harvest the positive-pair diagonal into g_pos.
// ---------------------------------------------------------------------------
#define BKB 64               // K bytes per stage
#define NKSTEP (D / BKB)     // 8
#define RPITCH 80            // padded row pitch (bytes)
#define A_BYTES (128 * RPITCH)       // 10240
#define STAGE_BYTES (2 * A_BYTES)    // 20480 (A then B)
#define NSTAGE 4
#define DYN_SMEM (NSTAGE * STAGE_BYTES)   // 81920

__device__ __forceinline__ uint32_t smem_u32(const void* p) {
    uint32_t a;
    asm("{ .reg .u64 t; cvta.to.shared.u64 t, %1; cvt.u32.u64 %0, t; }"
        : "=r"(a) : "l"(p));
    return a;
}

__device__ __forceinline__ void load_stage(uint32_t sbase,
                                           const uint8_t* gA,
                                           const uint8_t* gB,
                                           int kt, int t) {
    const int koff = kt * BKB;
    #pragma unroll
    for (int p = 0; p < 2; ++p) {
        int idx = t + p * 256;          // 0..511
        int row = idx >> 2;             // 0..127
        int cc = idx & 3;               // 16B chunk within 64B
        uint32_t so = (uint32_t)(row * RPITCH + cc * 16);
        const size_t go = (size_t)row * D + koff + cc * 16;
        CP_ASYNC16(sbase + so, gA + go);
        CP_ASYNC16(sbase + A_BYTES + so, gB + go);
    }
}

__global__ __launch_bounds__(256, 2) void gemm_exp_kernel() {
    extern __shared__ uint8_t smem[];
    __shared__ float rowsum[2][128];
    __shared__ float colsum_s[4][128];

    const int ti = blockIdx.x;
    const int tj = blockIdx.y;
    if (tj < ti) return;                 // symmetric: upper triangle only

    const int t = threadIdx.x;
    const int lane = t & 31;
    const int wid = t >> 5;
    const int wm = wid & 3;              // warp row 0..3
    const int wn = wid >> 2;             // warp col 0..1

    const uint32_t sb = smem_u32(smem);

    float c[2][8][4];
    #pragma unroll
    for (int mi = 0; mi < 2; ++mi)
        #pragma unroll
        for (int ni = 0; ni < 8; ++ni)
            #pragma unroll
            for (int q = 0; q < 4; ++q) c[mi][ni][q] = 0.0f;

    const uint8_t* gA = g_z8 + (size_t)ti * 128 * D;
    const uint8_t* gB = g_z8 + (size_t)tj * 128 * D;

    // prologue: stages 0..2
    load_stage(sb + 0 * STAGE_BYTES, gA, gB, 0, t); CP_COMMIT;
    load_stage(sb + 1 * STAGE_BYTES, gA, gB, 1, t); CP_COMMIT;
    load_stage(sb + 2 * STAGE_BYTES, gA, gB, 2, t); CP_COMMIT;

    for (int kt = 0; kt < NKSTEP; ++kt) {
        if (kt < 6)       CP_WAIT(2);
        else if (kt == 6) CP_WAIT(1);
        else              CP_WAIT(0);
        __syncthreads();

        // prefetch stage kt+3 into ring slot (slot kt-1 consumed before the
        // barrier above)
        if (kt + 3 < NKSTEP) {
            load_stage(sb + (uint32_t)((kt + 3) & 3) * STAGE_BYTES,
                       gA, gB, kt + 3, t);
            CP_COMMIT;
        }

        const uint32_t aBase = sb + (uint32_t)(kt & 3) * STAGE_BYTES;
        const uint32_t bBase = aBase + A_BYTES;

        #pragma unroll
        for (int ks = 0; ks < 2; ++ks) {
            const int kb = ks * 32;      // byte offset of k32 block
            uint32_t af[2][4];
            #pragma unroll
            for (int mi = 0; mi < 2; ++mi) {
                int r = wm * 32 + mi * 16 + (lane & 15);
                int colb = kb + (lane >> 4) * 16;
                uint32_t addr = aBase + r * RPITCH + colb;
                asm volatile(
                    "ldmatrix.sync.aligned.m8n8.x4.shared.b16 "
                    "{%0,%1,%2,%3}, [%4];"
                    : "=r"(af[mi][0]), "=r"(af[mi][1]),
                      "=r"(af[mi][2]), "=r"(af[mi][3])
                    : "r"(addr));
            }
            uint32_t bfr[8][2];
            #pragma unroll
            for (int nb = 0; nb < 4; ++nb) {
                int nr = wn * 64 + nb * 16 + ((lane >> 4) & 1) * 8 + (lane & 7);
                int colb = kb + ((lane >> 3) & 1) * 16;
                uint32_t addr = bBase + nr * RPITCH + colb;
                asm volatile(
                    "ldmatrix.sync.aligned.m8n8.x4.shared.b16 "
                    "{%0,%1,%2,%3}, [%4];"
                    : "=r"(bfr[2 * nb][0]), "=r"(bfr[2 * nb][1]),
                      "=r"(bfr[2 * nb + 1][0]), "=r"(bfr[2 * nb + 1][1])
                    : "r"(addr));
            }
            #pragma unroll
            for (int mi = 0; mi < 2; ++mi)
                #pragma unroll
                for (int ni = 0; ni < 8; ++ni) {
                    asm volatile(
                        "mma.sync.aligned.m16n8k32.row.col.f32.e4m3.e4m3.f32 "
                        "{%0,%1,%2,%3}, {%4,%5,%6,%7}, {%8,%9}, {%0,%1,%2,%3};"
                        : "+f"(c[mi][ni][0]), "+f"(c[mi][ni][1]),
                          "+f"(c[mi][ni][2]), "+f"(c[mi][ni][3])
                        : "r"(af[mi][0]), "r"(af[mi][1]),
                          "r"(af[mi][2]), "r"(af[mi][3]),
                          "r"(bfr[ni][0]), "r"(bfr[ni][1]));
                }
        }
    }

    // Epilogue: c := exp(2*sim) (diag masked to 0). acc = 256*sim.
    // m16n8 layout: c[rr*2+q] -> row=lane/4+rr*8, col=2*(lane%4)+q.
    // Pair tiles (tj == ti+32) harvest pos = 2*sim(i, i+B) from the local
    // diagonal before the exp overwrite (single writer per entry).
    const bool diag = (ti == tj);
    const bool pairTile = (tj == ti + (B_ROWS / 128));
    #pragma unroll
    for (int mi = 0; mi < 2; ++mi)
        #pragma unroll
        for (int rr = 0; rr < 2; ++rr) {
            int grow = ti * 128 + wm * 32 + mi * 16 + rr * 8 + (lane >> 2);
            #pragma unroll
            for (int ni = 0; ni < 8; ++ni)
                #pragma unroll
                for (int q = 0; q < 2; ++q) {
                    int gcol = tj * 128 + wn * 64 + ni * 8 + 2 * (lane & 3) + q;
                    float v = c[mi][ni][rr * 2 + q];
                    if (pairTile && gcol == grow + B_ROWS)
                        g_pos[grow] = v * POS_MUL;
                    c[mi][ni][rr * 2 + q] =
                        (grow == gcol) ? 0.0f : fast_exp2(v * EPI_MUL);
                }
        }

    // Row sums (rows of block ti)
    #pragma unroll
    for (int mi = 0; mi < 2; ++mi)
        #pragma unroll
        for (int rr = 0; rr < 2; ++rr) {
            int lrow = wm * 32 + mi * 16 + rr * 8 + (lane >> 2);
            float s = 0.0f;
            #pragma unroll
            for (int ni = 0; ni < 8; ++ni)
                #pragma unroll
                for (int q = 0; q < 2; ++q) s += c[mi][ni][rr * 2 + q];
            s += __shfl_xor_sync(0xffffffff, s, 1);
            s += __shfl_xor_sync(0xffffffff, s, 2);
            if ((lane & 3) == 0) rowsum[wn][lrow] = s;
        }

    // Column sums (rows of block tj) — only off-diagonal tiles
    if (!diag) {
        #pragma unroll
        for (int ni = 0; ni < 8; ++ni)
            #pragma unroll
            for (int q = 0; q < 2; ++q) {
                float s = c[0][ni][q] + c[0][ni][2 + q] +
                          c[1][ni][q] + c[1][ni][2 + q];
                s += __shfl_xor_sync(0xffffffff, s, 4);
                s += __shfl_xor_sync(0xffffffff, s, 8);
                s += __shfl_xor_sync(0xffffffff, s, 16);
                if ((lane >> 2) == 0) {
                    int lcol = wn * 64 + ni * 8 + 2 * (lane & 3) + q;
                    colsum_s[wm][lcol] = s;
                }
            }
    }
    __syncthreads();

    if (t < 128) {
        g_partial[(size_t)tj * NTOT + (size_t)ti * 128 + t] =
            rowsum[0][t] + rowsum[1][t];
        if (!diag)
            g_partial[(size_t)ti * NTOT + (size_t)tj * 128 + t] =
                colsum_s[0][t] + colsum_s[1][t] +
                colsum_s[2][t] + colsum_s[3][t];
    }
}

// ---------------------------------------------------------------------------
// K3: per-row loss (thread per row; partial gather is coalesced across
// threads since consecutive rows are consecutive addresses per slot) +
// fused deterministic finalize. 32 blocks x 256 threads.
// ---------------------------------------------------------------------------
__global__ void rowloss_kernel(float* __restrict__ out) {
    const int t = threadIdx.x;
    const int row = blockIdx.x * 256 + t;

    float s = 0.0f;
    #pragma unroll 16
    for (int k = 0; k < NT; ++k)
        s += g_partial[(size_t)k * NTOT + row];

    float pos = g_pos[row & (B_ROWS - 1)];   // row and row+B share the value
    g_rowloss[row] = fast_log(s) - pos;

    // last-block finalize (deterministic fixed-order sum; no FP atomics)
    __shared__ int is_last;
    __shared__ float sm[256];
    __threadfence();
    __syncthreads();
    if (t == 0)
        is_last = (atomicAdd(&g_ctr, 1) == (int)gridDim.x - 1);
    __syncthreads();
    if (is_last) {
        __threadfence();
        float acc = 0.0f;
        for (int i = t; i < NTOT; i += 256) acc += g_rowloss[i];
        sm[t] = acc;
        __syncthreads();
        #pragma unroll
        for (int st = 128; st > 0; st >>= 1) {
            if (t < st) sm[t] += sm[t + st];
            __syncthreads();
        }
        if (t == 0) {
            g_ctr = 0;   // reset for next graph replay
            out[0] = sm[0] * (1.0f / NTOT);
        }
    }
}

// ---------------------------------------------------------------------------
extern "C" void kernel_launch(void* const* d_in, const int* in_sizes, int n_in,
                              void* d_out, int out_size) {
    const float* h1 = (const float*)d_in[0];
    const float* h2 = (const float*)d_in[1];
    float* out = (float*)d_out;

    static bool attr_set = false;
    if (!attr_set) {
        cudaFuncSetAttribute(gemm_exp_kernel,
                             cudaFuncAttributeMaxDynamicSharedMemorySize,
                             DYN_SMEM);
        attr_set = true;
    }

    normalize_kernel<<<NTOT, 128>>>(h1, h2);
    gemm_exp_kernel<<<dim3(NT, NT), 256, DYN_SMEM>>>();
    rowloss_kernel<<<NTOT / 256, 256>>>(out);
}

// round 17
// speedup vs baseline: 1.1832x; 1.0177x over previous
#include <cuda_runtime.h>
#include <cuda_bf16.h>
#include <cuda_fp8.h>
#include <cstdint>

// ---------------------------------------------------------------------------
// Problem constants
// ---------------------------------------------------------------------------
#define B_ROWS 4096
#define NTOT   8192          // 2B
#define D      512
#define NT     64            // NTOT / 128 tiles per dim
#define TEMP_INV 2.0f
#define LOG2E_2  2.8853900817779268f  // 2/ln2 : exp(2x)=2^(x*2/ln2)
#define LN2      0.6931471805599453f
#define Z_SCALE  16.0f                // fp8 pre-scale (avoid subnormals)
// accumulated sim is scaled by Z_SCALE^2=256; fold into exp2 multiplier
#define EPI_MUL  (LOG2E_2 / 256.0f)
#define POS_MUL  (TEMP_INV / 256.0f)  // pos term: 2*sim = acc * 2/256

// ---------------------------------------------------------------------------
// Scratch (__device__ globals; no allocation allowed)
// ---------------------------------------------------------------------------
__device__ uint8_t g_z8[(size_t)NTOT * D];         // 4 MB normalized e4m3*16
__device__ float g_partial[(size_t)NT * NTOT];     // 2 MB partial row sums
__device__ float g_pos[B_ROWS];                    // 2*sim(i, i+B), harvested
__device__ float g_rowloss[NTOT];
__device__ int   g_ctr;                            // last-block counter (resets)

// ---------------------------------------------------------------------------
// Helpers
// ---------------------------------------------------------------------------
__device__ __forceinline__ float fast_exp2(float x) {
    float r; asm("ex2.approx.ftz.f32 %0, %1;" : "=f"(r) : "f"(x)); return r;
}
__device__ __forceinline__ float fast_log(float x) {
    float r; asm("lg2.approx.f32 %0, %1;" : "=f"(r) : "f"(x)); return r * LN2;
}

#define CP_ASYNC16(dst32, srcp)                                              \
    asm volatile("cp.async.cg.shared.global [%0], [%1], 16;\n" ::            \
                     "r"(dst32), "l"(srcp))
#define CP_COMMIT  asm volatile("cp.async.commit_group;\n" ::)
#define CP_WAIT(n) asm volatile("cp.async.wait_group %0;\n" :: "n"(n))

// ---------------------------------------------------------------------------
// K1: row-normalize (eps clamp), emit e4m3*16. Warp-per-row: no block sync,
// no shared memory. 1024 blocks x 256 threads (8 warps = 8 rows per block).
// Lane reads 4 coalesced float4s (MLP 4), shfl-reduces, stores 4 coalesced
// uint32s of packed fp8.
// ---------------------------------------------------------------------------
__global__ void normalize_kernel(const float* __restrict__ h1,
                                 const float* __restrict__ h2) {
    const int lane = threadIdx.x & 31;
    const int w = threadIdx.x >> 5;
    const int row = blockIdx.x * 8 + w;
    const float* src = (row < B_ROWS) ? (h1 + (size_t)row * D)
                                      : (h2 + (size_t)(row - B_ROWS) * D);
    const float4* src4 = reinterpret_cast<const float4*>(src);

    float4 v[4];
    #pragma unroll
    for (int p = 0; p < 4; ++p) v[p] = src4[lane + p * 32];

    float s = 0.0f;
    #pragma unroll
    for (int p = 0; p < 4; ++p)
        s += v[p].x * v[p].x + v[p].y * v[p].y +
             v[p].z * v[p].z + v[p].w * v[p].w;
    #pragma unroll
    for (int o = 16; o > 0; o >>= 1) s += __shfl_xor_sync(0xffffffff, s, o);

    const float s8 = Z_SCALE / fmaxf(sqrtf(s), 1e-8f);

    uint32_t* dst = reinterpret_cast<uint32_t*>(g_z8) + (size_t)row * (D / 4);
    #pragma unroll
    for (int p = 0; p < 4; ++p) {
        float2 p0 = make_float2(v[p].x * s8, v[p].y * s8);
        float2 p1 = make_float2(v[p].z * s8, v[p].w * s8);
        uint32_t lo = __nv_cvt_float2_to_fp8x2(p0, __NV_SATFINITE, __NV_E4M3);
        uint32_t hi = __nv_cvt_float2_to_fp8x2(p1, __NV_SATFINITE, __NV_E4M3);
        dst[lane + p * 32] = (lo & 0xffffu) | (hi << 16);
    }
}

// ---------------------------------------------------------------------------
// K2: fused FP8 GEMM tile + exp + row/col partial sums (round-8 proven
// shape: 64x64 grid, early-exit lower triangle). 4-stage cp.async ring,
// BK=64B (8 K-steps). 8 warps (4M x 2N), warp tile 32x64,
// mma.sync.m16n8k32 e4m3 f32acc. 80B row pitch -> conflict-free ldmatrix.
// Tiles with tj == ti+32 also harvest the positive-pair diagonal into g_pos.
// ---------------------------------------------------------------------------
#define BKB 64               // K bytes per stage
#define NKSTEP (D / BKB)     // 8
#define RPITCH 80            // padded row pitch (bytes)
#define A_BYTES (128 * RPITCH)       // 10240
#define STAGE_BYTES (2 * A_BYTES)    // 20480 (A then B)
#define NSTAGE 4
#define DYN_SMEM (NSTAGE * STAGE_BYTES)   // 81920

__device__ __forceinline__ uint32_t smem_u32(const void* p) {
    uint32_t a;
    asm("{ .reg .u64 t; cvta.to.shared.u64 t, %1; cvt.u32.u64 %0, t; }"
        : "=r"(a) : "l"(p));
    return a;
}

__device__ __forceinline__ void load_stage(uint32_t sbase,
                                           const uint8_t* gA,
                                           const uint8_t* gB,
                                           int kt, int t) {
    const int koff = kt * BKB;
    #pragma unroll
    for (int p = 0; p < 2; ++p) {
        int idx = t + p * 256;          // 0..511
        int row = idx >> 2;             // 0..127
        int cc = idx & 3;               // 16B chunk within 64B
        uint32_t so = (uint32_t)(row * RPITCH + cc * 16);
        const size_t go = (size_t)row * D + koff + cc * 16;
        CP_ASYNC16(sbase + so, gA + go);
        CP_ASYNC16(sbase + A_BYTES + so, gB + go);
    }
}

__global__ __launch_bounds__(256, 2) void gemm_exp_kernel() {
    extern __shared__ uint8_t smem[];
    __shared__ float rowsum[2][128];
    __shared__ float colsum_s[4][128];

    const int ti = blockIdx.x;
    const int tj = blockIdx.y;
    if (tj < ti) return;                 // symmetric: upper triangle only

    const int t = threadIdx.x;
    const int lane = t & 31;
    const int wid = t >> 5;
    const int wm = wid & 3;              // warp row 0..3
    const int wn = wid >> 2;             // warp col 0..1

    const uint32_t sb = smem_u32(smem);

    float c[2][8][4];
    #pragma unroll
    for (int mi = 0; mi < 2; ++mi)
        #pragma unroll
        for (int ni = 0; ni < 8; ++ni)
            #pragma unroll
            for (int q = 0; q < 4; ++q) c[mi][ni][q] = 0.0f;

    const uint8_t* gA = g_z8 + (size_t)ti * 128 * D;
    const uint8_t* gB = g_z8 + (size_t)tj * 128 * D;

    // prologue: stages 0..2
    load_stage(sb + 0 * STAGE_BYTES, gA, gB, 0, t); CP_COMMIT;
    load_stage(sb + 1 * STAGE_BYTES, gA, gB, 1, t); CP_COMMIT;
    load_stage(sb + 2 * STAGE_BYTES, gA, gB, 2, t); CP_COMMIT;

    for (int kt = 0; kt < NKSTEP; ++kt) {
        if (kt < 6)       CP_WAIT(2);
        else if (kt == 6) CP_WAIT(1);
        else              CP_WAIT(0);
        __syncthreads();

        // prefetch stage kt+3 into ring slot (slot kt-1 consumed before the
        // barrier above)
        if (kt + 3 < NKSTEP) {
            load_stage(sb + (uint32_t)((kt + 3) & 3) * STAGE_BYTES,
                       gA, gB, kt + 3, t);
            CP_COMMIT;
        }

        const uint32_t aBase = sb + (uint32_t)(kt & 3) * STAGE_BYTES;
        const uint32_t bBase = aBase + A_BYTES;

        #pragma unroll
        for (int ks = 0; ks < 2; ++ks) {
            const int kb = ks * 32;      // byte offset of k32 block
            uint32_t af[2][4];
            #pragma unroll
            for (int mi = 0; mi < 2; ++mi) {
                int r = wm * 32 + mi * 16 + (lane & 15);
                int colb = kb + (lane >> 4) * 16;
                uint32_t addr = aBase + r * RPITCH + colb;
                asm volatile(
                    "ldmatrix.sync.aligned.m8n8.x4.shared.b16 "
                    "{%0,%1,%2,%3}, [%4];"
                    : "=r"(af[mi][0]), "=r"(af[mi][1]),
                      "=r"(af[mi][2]), "=r"(af[mi][3])
                    : "r"(addr));
            }
            uint32_t bfr[8][2];
            #pragma unroll
            for (int nb = 0; nb < 4; ++nb) {
                int nr = wn * 64 + nb * 16 + ((lane >> 4) & 1) * 8 + (lane & 7);
                int colb = kb + ((lane >> 3) & 1) * 16;
                uint32_t addr = bBase + nr * RPITCH + colb;
                asm volatile(
                    "ldmatrix.sync.aligned.m8n8.x4.shared.b16 "
                    "{%0,%1,%2,%3}, [%4];"
                    : "=r"(bfr[2 * nb][0]), "=r"(bfr[2 * nb][1]),
                      "=r"(bfr[2 * nb + 1][0]), "=r"(bfr[2 * nb + 1][1])
                    : "r"(addr));
            }
            #pragma unroll
            for (int mi = 0; mi < 2; ++mi)
                #pragma unroll
                for (int ni = 0; ni < 8; ++ni) {
                    asm volatile(
                        "mma.sync.aligned.m16n8k32.row.col.f32.e4m3.e4m3.f32 "
                        "{%0,%1,%2,%3}, {%4,%5,%6,%7}, {%8,%9}, {%0,%1,%2,%3};"
                        : "+f"(c[mi][ni][0]), "+f"(c[mi][ni][1]),
                          "+f"(c[mi][ni][2]), "+f"(c[mi][ni][3])
                        : "r"(af[mi][0]), "r"(af[mi][1]),
                          "r"(af[mi][2]), "r"(af[mi][3]),
                          "r"(bfr[ni][0]), "r"(bfr[ni][1]));
                }
        }
    }

    // Epilogue: c := exp(2*sim) (diag masked to 0). acc = 256*sim.
    // m16n8 layout: c[rr*2+q] -> row=lane/4+rr*8, col=2*(lane%4)+q.
    // Pair tiles (tj == ti+32) harvest pos = 2*sim(i, i+B) from the local
    // diagonal before the exp overwrite (single writer per entry).
    const bool diag = (ti == tj);
    const bool pairTile = (tj == ti + (B_ROWS / 128));
    #pragma unroll
    for (int mi = 0; mi < 2; ++mi)
        #pragma unroll
        for (int rr = 0; rr < 2; ++rr) {
            int grow = ti * 128 + wm * 32 + mi * 16 + rr * 8 + (lane >> 2);
            #pragma unroll
            for (int ni = 0; ni < 8; ++ni)
                #pragma unroll
                for (int q = 0; q < 2; ++q) {
                    int gcol = tj * 128 + wn * 64 + ni * 8 + 2 * (lane & 3) + q;
                    float v = c[mi][ni][rr * 2 + q];
                    if (pairTile && gcol == grow + B_ROWS)
                        g_pos[grow] = v * POS_MUL;
                    c[mi][ni][rr * 2 + q] =
                        (grow == gcol) ? 0.0f : fast_exp2(v * EPI_MUL);
                }
        }

    // Row sums (rows of block ti)
    #pragma unroll
    for (int mi = 0; mi < 2; ++mi)
        #pragma unroll
        for (int rr = 0; rr < 2; ++rr) {
            int lrow = wm * 32 + mi * 16 + rr * 8 + (lane >> 2);
            float s = 0.0f;
            #pragma unroll
            for (int ni = 0; ni < 8; ++ni)
                #pragma unroll
                for (int q = 0; q < 2; ++q) s += c[mi][ni][rr * 2 + q];
            s += __shfl_xor_sync(0xffffffff, s, 1);
            s += __shfl_xor_sync(0xffffffff, s, 2);
            if ((lane & 3) == 0) rowsum[wn][lrow] = s;
        }

    // Column sums (rows of block tj) — only off-diagonal tiles
    if (!diag) {
        #pragma unroll
        for (int ni = 0; ni < 8; ++ni)
            #pragma unroll
            for (int q = 0; q < 2; ++q) {
                float s = c[0][ni][q] + c[0][ni][2 + q] +
                          c[1][ni][q] + c[1][ni][2 + q];
                s += __shfl_xor_sync(0xffffffff, s, 4);
                s += __shfl_xor_sync(0xffffffff, s, 8);
                s += __shfl_xor_sync(0xffffffff, s, 16);
                if ((lane >> 2) == 0) {
                    int lcol = wn * 64 + ni * 8 + 2 * (lane & 3) + q;
                    colsum_s[wm][lcol] = s;
                }
            }
    }
    __syncthreads();

    if (t < 128) {
        g_partial[(size_t)tj * NTOT + (size_t)ti * 128 + t] =
            rowsum[0][t] + rowsum[1][t];
        if (!diag)
            g_partial[(size_t)ti * NTOT + (size_t)tj * 128 + t] =
                colsum_s[0][t] + colsum_s[1][t] +
                colsum_s[2][t] + colsum_s[3][t];
    }
}

// ---------------------------------------------------------------------------
// K3: per-row loss (thread per row; partial gather is coalesced across
// threads since consecutive rows are consecutive addresses per slot) +
// fused deterministic finalize. 32 blocks x 256 threads.
// ---------------------------------------------------------------------------
__global__ void rowloss_kernel(float* __restrict__ out) {
    const int t = threadIdx.x;
    const int row = blockIdx.x * 256 + t;

    float s = 0.0f;
    #pragma unroll 16
    for (int k = 0; k < NT; ++k)
        s += g_partial[(size_t)k * NTOT + row];

    float pos = g_pos[row & (B_ROWS - 1)];   // row and row+B share the value
    g_rowloss[row] = fast_log(s) - pos;

    // last-block finalize (deterministic fixed-order sum; no FP atomics)
    __shared__ int is_last;
    __shared__ float sm[256];
    __threadfence();
    __syncthreads();
    if (t == 0)
        is_last = (atomicAdd(&g_ctr, 1) == (int)gridDim.x - 1);
    __syncthreads();
    if (is_last) {
        __threadfence();
        float acc = 0.0f;
        for (int i = t; i < NTOT; i += 256) acc += g_rowloss[i];
        sm[t] = acc;
        __syncthreads();
        #pragma unroll
        for (int st = 128; st > 0; st >>= 1) {
            if (t < st) sm[t] += sm[t + st];
            __syncthreads();
        }
        if (t == 0) {
            g_ctr = 0;   // reset for next graph replay
            out[0] = sm[0] * (1.0f / NTOT);
        }
    }
}

// ---------------------------------------------------------------------------
extern "C" void kernel_launch(void* const* d_in, const int* in_sizes, int n_in,
                              void* d_out, int out_size) {
    const float* h1 = (const float*)d_in[0];
    const float* h2 = (const float*)d_in[1];
    float* out = (float*)d_out;

    static bool attr_set = false;
    if (!attr_set) {
        cudaFuncSetAttribute(gemm_exp_kernel,
                             cudaFuncAttributeMaxDynamicSharedMemorySize,
                             DYN_SMEM);
        attr_set = true;
    }

    normalize_kernel<<<NTOT / 8, 256>>>(h1, h2);
    gemm_exp_kernel<<<dim3(NT, NT), 256, DYN_SMEM>>>();
    rowloss_kernel<<<NTOT / 256, 256>>>(out);
}